// round 14
// baseline (speedup 1.0000x reference)
#include <cuda_runtime.h>

// MultiCellLSTM: B=4096, T=512, H=64, gates 4H=256.
// R14: R13 with register-pressure surgery to enable cross-step pipelining:
//  - bias/input-weights moved from 72 live registers to smem (u64-paired,
//    0.5-prescaled for i,f,o), loaded per-step in the EW phase (f32x2 fold)
//  - j-loop unroll 8; barrier-free loop + freed regs let ptxas hoist the
//    next step's independent weight LDS into the EW/MUFU tail
// 7 warps x 147 CTAs, 4 rows/warp, plain-h + reg-dup (R12), tanh.approx.

typedef unsigned long long u64;

#define NTHR   224                  // 7 warps
#define NCTA   147                  // 147*7 = 1029 warps >= 1024 needed
#define NWARP  7
#define WS_U64 (3 * 64 * 128)       // 24576 u64 : recurrent weights (192KB)
#define CMB_U64 (3 * 4 * 128)       // 1536  u64 : bias + input-weight cols (12KB)
#define HD_U64 (2 * NWARP * 4 * 32) // 1792  u64 : double-buffered plain h (14KB)
#define SMEM_BYTES ((WS_U64 + CMB_U64 + HD_U64) * 8)   // 223232

__device__ __forceinline__ float ex2f(float x) { float y; asm("ex2.approx.f32 %0, %1;" : "=f"(y) : "f"(x)); return y; }
__device__ __forceinline__ float rcpf(float x) { float y; asm("rcp.approx.f32 %0, %1;" : "=f"(y) : "f"(x)); return y; }
__device__ __forceinline__ float sigp(float x) { return rcpf(1.0f + ex2f(-1.4426950408889634f * x)); }  // final out only
__device__ __forceinline__ float tha(float x) { float y; asm("tanh.approx.f32 %0, %1;" : "=f"(y) : "f"(x)); return y; }

__device__ __forceinline__ u64 pk2(float a, float b) { u64 r; asm("mov.b64 %0, {%1, %2};" : "=l"(r) : "f"(a), "f"(b)); return r; }
__device__ __forceinline__ void up2(u64 v, float& a, float& b) { asm("mov.b64 {%0, %1}, %2;" : "=f"(a), "=f"(b) : "l"(v)); }
__device__ __forceinline__ u64 ffma2(u64 a, u64 b, u64 c) { u64 d; asm("fma.rn.f32x2 %0, %1, %2, %3;" : "=l"(d) : "l"(a), "l"(b), "l"(c)); return d; }
__device__ __forceinline__ u64 add2(u64 a, u64 b) { u64 d; asm("add.rn.f32x2 %0, %1, %2;" : "=l"(d) : "l"(a), "l"(b)); return d; }

// One LSTM step for cell type TY (0: x1+x2+x3, 1: x1+x2, 2: x1 only).
// Lane owns units {2l,2l+1} x 4 rows. Weight k-row layout (1024B):
//   16B slot = l*32 + ((h ^ (l>>2))&1)*16; h=0 -> classes(i,f), h=1 -> (g,o).
// h row buffer: 64 floats plain (256B); lane l owns bytes l*8..l*8+7.
// cmb: per cell 4KB = arrays [bias, w_x1, w_x2, w_x3] x 128 u64 slots
// (same swizzle as weights); classes i,f,o pre-scaled by 0.5 (exact).
template<int TY>
__device__ __forceinline__ void do_step(
    const char* __restrict__ wsB, const char* __restrict__ cmB,
    const char* hrd,   // read h buffer (4 rows x 256B)
    char* hwr,         // write h buffer
    int lane, int offA, int offB,
    const float (&xv1)[4], const float (&xv2)[4], const float (&xv3)[4],
    float (&cst)[4][2], float (&hl)[4][2])
{
    const char* wcell = wsB + TY * 65536;   // 64 k-rows * 1024B

    u64 acc[4][4];  // [class i,f,g,o][row] -- zero-init: chains start free
    #pragma unroll
    for (int q = 0; q < 4; q++)
        #pragma unroll
        for (int r = 0; r < 4; r++) acc[q][r] = 0ull;

    // recurrent: j covers k = 4j..4j+3. One broadcast LDS.128 per (j,row)
    // delivers 4 h values; dup'd into f32x2 operands in registers.
    #pragma unroll 8
    for (int j = 0; j < 16; j++) {
        const char* base = wcell + j * 4096;
        ulonglong2 wA0 = *(const ulonglong2*)(base + offA);
        ulonglong2 wB0 = *(const ulonglong2*)(base + offB);
        ulonglong2 wA1 = *(const ulonglong2*)(base + 1024 + offA);
        ulonglong2 wB1 = *(const ulonglong2*)(base + 1024 + offB);
        ulonglong2 wA2 = *(const ulonglong2*)(base + 2048 + offA);
        ulonglong2 wB2 = *(const ulonglong2*)(base + 2048 + offB);
        ulonglong2 wA3 = *(const ulonglong2*)(base + 3072 + offA);
        ulonglong2 wB3 = *(const ulonglong2*)(base + 3072 + offB);
        ulonglong2 hv0 = *(const ulonglong2*)(hrd + 0 * 256 + j * 16);
        ulonglong2 hv1 = *(const ulonglong2*)(hrd + 1 * 256 + j * 16);
        ulonglong2 hv2 = *(const ulonglong2*)(hrd + 2 * 256 + j * 16);
        ulonglong2 hv3 = *(const ulonglong2*)(hrd + 3 * 256 + j * 16);
        ulonglong2 hvv[4] = {hv0, hv1, hv2, hv3};
        #pragma unroll
        for (int r = 0; r < 4; r++) {
            float h0, h1, h2, h3;
            up2(hvv[r].x, h0, h1);
            up2(hvv[r].y, h2, h3);
            u64 d0 = pk2(h0, h0), d1 = pk2(h1, h1), d2 = pk2(h2, h2), d3 = pk2(h3, h3);
            acc[0][r] = ffma2(wA0.x, d0, acc[0][r]);
            acc[1][r] = ffma2(wA0.y, d0, acc[1][r]);
            acc[2][r] = ffma2(wB0.x, d0, acc[2][r]);
            acc[3][r] = ffma2(wB0.y, d0, acc[3][r]);
            acc[0][r] = ffma2(wA1.x, d1, acc[0][r]);
            acc[1][r] = ffma2(wA1.y, d1, acc[1][r]);
            acc[2][r] = ffma2(wB1.x, d1, acc[2][r]);
            acc[3][r] = ffma2(wB1.y, d1, acc[3][r]);
            acc[0][r] = ffma2(wA2.x, d2, acc[0][r]);
            acc[1][r] = ffma2(wA2.y, d2, acc[1][r]);
            acc[2][r] = ffma2(wB2.x, d2, acc[2][r]);
            acc[3][r] = ffma2(wB2.y, d2, acc[3][r]);
            acc[0][r] = ffma2(wA3.x, d3, acc[0][r]);
            acc[1][r] = ffma2(wA3.y, d3, acc[1][r]);
            acc[2][r] = ffma2(wB3.x, d3, acc[2][r]);
            acc[3][r] = ffma2(wB3.y, d3, acc[3][r]);
        }
    }

    // EW: load cmb from smem (transient), fold input terms in f32x2, LSTM cell.
    const char* cc = cmB + TY * 4096;
    ulonglong2 bA  = *(const ulonglong2*)(cc + offA);
    ulonglong2 bB  = *(const ulonglong2*)(cc + offB);
    ulonglong2 w1A = *(const ulonglong2*)(cc + 1024 + offA);
    ulonglong2 w1B = *(const ulonglong2*)(cc + 1024 + offB);
    ulonglong2 w2A = {}, w2B = {}, w3A = {}, w3B = {};
    if constexpr (TY <= 1) {
        w2A = *(const ulonglong2*)(cc + 2048 + offA);
        w2B = *(const ulonglong2*)(cc + 2048 + offB);
    }
    if constexpr (TY == 0) {
        w3A = *(const ulonglong2*)(cc + 3072 + offA);
        w3B = *(const ulonglong2*)(cc + 3072 + offB);
    }

    #pragma unroll
    for (int r = 0; r < 4; r++) {
        u64 xd1 = pk2(xv1[r], xv1[r]);
        u64 pI = ffma2(w1A.x, xd1, bA.x);
        u64 pF = ffma2(w1A.y, xd1, bA.y);
        u64 pG = ffma2(w1B.x, xd1, bB.x);
        u64 pO = ffma2(w1B.y, xd1, bB.y);
        if constexpr (TY <= 1) {
            u64 xd2 = pk2(xv2[r], xv2[r]);
            pI = ffma2(w2A.x, xd2, pI);
            pF = ffma2(w2A.y, xd2, pF);
            pG = ffma2(w2B.x, xd2, pG);
            pO = ffma2(w2B.y, xd2, pO);
        }
        if constexpr (TY == 0) {
            u64 xd3 = pk2(xv3[r], xv3[r]);
            pI = ffma2(w3A.x, xd3, pI);
            pF = ffma2(w3A.y, xd3, pF);
            pG = ffma2(w3B.x, xd3, pG);
            pO = ffma2(w3B.y, xd3, pO);
        }
        float gi0, gi1, gf0, gf1, gg0, gg1, go0, go1;
        up2(add2(acc[0][r], pI), gi0, gi1);
        up2(add2(acc[1][r], pF), gf0, gf1);
        up2(add2(acc[2][r], pG), gg0, gg1);
        up2(add2(acc[3][r], pO), go0, go1);
        // classes i,f,o hold 0.5*gate -> sigmoid = 0.5*tanh(acc)+0.5
        float si0 = fmaf(0.5f, tha(gi0), 0.5f);
        float si1 = fmaf(0.5f, tha(gi1), 0.5f);
        float sf0 = fmaf(0.5f, tha(gf0), 0.5f);
        float sf1 = fmaf(0.5f, tha(gf1), 0.5f);
        float so0 = fmaf(0.5f, tha(go0), 0.5f);
        float so1 = fmaf(0.5f, tha(go1), 0.5f);
        float tg0 = tha(gg0);
        float tg1 = tha(gg1);
        float c0 = fmaf(sf0, cst[r][0], si0 * tg0);
        float c1 = fmaf(sf1, cst[r][1], si1 * tg1);
        cst[r][0] = c0; cst[r][1] = c1;
        float h0 = so0 * tha(c0);
        float h1 = so1 * tha(c1);
        hl[r][0] = h0; hl[r][1] = h1;
        *(u64*)(hwr + r * 256 + lane * 8) = pk2(h0, h1);   // plain (h_u0, h_u1)
    }
}

__global__ __launch_bounds__(NTHR, 1) void mclstm_kernel(
    const float* __restrict__ x1, const float* __restrict__ x2, const float* __restrict__ x3,
    const float* __restrict__ Wih3, const float* __restrict__ Whh3,
    const float* __restrict__ bih3, const float* __restrict__ bhh3,
    const float* __restrict__ Wih2, const float* __restrict__ Whh2,
    const float* __restrict__ bih2, const float* __restrict__ bhh2,
    const float* __restrict__ Wih1, const float* __restrict__ Whh1,
    const float* __restrict__ bih1, const float* __restrict__ bhh1,
    const float* __restrict__ Wout, const float* __restrict__ bOut,
    float* __restrict__ out)
{
    extern __shared__ u64 sm[];
    u64* ws   = sm;
    u64* cmb  = ws + WS_U64;    // 3 cells x 4 arrays x 128 slots
    u64* hbuf = cmb + CMB_U64;  // [par][7 warps][4 rows][32 u64]

    const int tid = threadIdx.x;

    // ---- stage recurrent weights: ws[(ty*64+k)*128 + slot] ----
    // slot s -> lane l=s>>2, 16B half swz=(s>>1)&1, col=s&1;
    // logical half h = swz ^ ((l>>2)&1); class q = 2h+col; units (2l,2l+1).
    // Classes i(0), f(1), o(3) scaled by 0.5 (exact).
    for (int idx = tid; idx < WS_U64; idx += NTHR) {
        int ty = idx >> 13, rem = idx & 8191, k = rem >> 7, s = rem & 127;
        int l = s >> 2, swz = (s >> 1) & 1, col = s & 1;
        int h = swz ^ ((l >> 2) & 1);
        int q = 2 * h + col;
        const float* W = (ty == 0) ? Whh3 : (ty == 1) ? Whh2 : Whh1;
        int g0 = (q * 64 + 2 * l) * 64 + k;
        float sc = (q == 2) ? 1.0f : 0.5f;
        ws[idx] = pk2(W[g0] * sc, W[g0 + 64] * sc);
    }
    // ---- stage cmb (bias+bhh, input-weight cols), same swizzle, 0.5-scaled ----
    for (int idx = tid; idx < CMB_U64; idx += NTHR) {
        int ty = idx >> 9, rem = idx & 511, arr = rem >> 7, s = rem & 127;
        int l = s >> 2, swz = (s >> 1) & 1, col = s & 1;
        int h = swz ^ ((l >> 2) & 1);
        int q = 2 * h + col;
        int j0 = q * 64 + 2 * l, j1 = j0 + 1;
        const float *bi, *bh, *wi; int wic;
        if (ty == 0)      { bi = bih3; bh = bhh3; wi = Wih3; wic = 3; }
        else if (ty == 1) { bi = bih2; bh = bhh2; wi = Wih2; wic = 2; }
        else              { bi = bih1; bh = bhh1; wi = Wih1; wic = 1; }
        float sc = (q == 2) ? 1.0f : 0.5f;
        float a, b;
        if (arr == 0) { a = (bi[j0] + bh[j0]) * sc; b = (bi[j1] + bh[j1]) * sc; }
        else {
            int cx = arr - 1;
            if (cx < wic) { a = wi[j0 * wic + cx] * sc; b = wi[j1 * wic + cx] * sc; }
            else          { a = 0.f; b = 0.f; }
        }
        cmb[idx] = pk2(a, b);
    }
    for (int idx = tid; idx < HD_U64; idx += NTHR) hbuf[idx] = 0ull;

    const int lane = tid & 31, w = tid >> 5;
    const int gw   = blockIdx.x * NWARP + w;     // global warp id
    const int row0 = gw * 4;
    const int u0 = 2 * lane;

    __syncthreads();

    if (row0 >= 4096) return;   // surplus warps (tail CTA) exit after init

    const int s0   = ((lane >> 2) & 1) * 16;
    const int offA = lane * 32 + s0;        // classes (i,f)
    const int offB = lane * 32 + 16 - s0;   // classes (g,o)

    const char* wsB = (const char*)ws;
    const char* cmB = (const char*)cmb;
    char* hb0 = (char*)hbuf + (size_t)w * 1024;      // par 0: warp-private 1KB
    char* hb1 = hb0 + NWARP * 1024;                  // par 1

    float cst[4][2], hl[4][2];
    #pragma unroll
    for (int r = 0; r < 4; r++) { cst[r][0] = cst[r][1] = 0.f; hl[r][0] = hl[r][1] = 0.f; }

    const float* x1r = x1 + (size_t)row0 * 512;
    const float* x2r = x2 + (size_t)row0 * 256;
    const float* x3r = x3 + (size_t)row0 * 128;

    for (int b = 0; b < 128; b++) {
        float a1v[4][4], a2v[4][2], a3v[4];
        #pragma unroll
        for (int r = 0; r < 4; r++) {
            float4 v = *(const float4*)(x1r + (size_t)r * 512 + b * 4);
            a1v[r][0] = v.x; a1v[r][1] = v.y; a1v[r][2] = v.z; a1v[r][3] = v.w;
            float2 u = *(const float2*)(x2r + (size_t)r * 256 + b * 2);
            a2v[r][0] = u.x; a2v[r][1] = u.y;
            a3v[r] = x3r[(size_t)r * 128 + b];
        }
        float t1[4], t2[4];

        // x consumed only in the EW phase -> LDG latency hidden by m-loop
        #pragma unroll
        for (int r = 0; r < 4; r++) { t1[r] = a1v[r][0]; t2[r] = a2v[r][0]; }
        do_step<0>(wsB, cmB, hb0, hb1, lane, offA, offB, t1, t2, a3v, cst, hl);  // t%4==0

        #pragma unroll
        for (int r = 0; r < 4; r++) t1[r] = a1v[r][1];
        do_step<2>(wsB, cmB, hb1, hb0, lane, offA, offB, t1, t1, t1, cst, hl);   // t%4==1

        #pragma unroll
        for (int r = 0; r < 4; r++) { t1[r] = a1v[r][2]; t2[r] = a2v[r][1]; }
        do_step<1>(wsB, cmB, hb0, hb1, lane, offA, offB, t1, t2, t2, cst, hl);   // t%4==2

        #pragma unroll
        for (int r = 0; r < 4; r++) t1[r] = a1v[r][3];
        do_step<2>(wsB, cmB, hb1, hb0, lane, offA, offB, t1, t1, t1, cst, hl);   // t%4==3
    }

    // out[row] = sigmoid(h . Wout + bOut): lane holds 2 units per row
    const float wo0 = Wout[u0], wo1 = Wout[u0 + 1];
    const float bo = bOut[0];
    #pragma unroll
    for (int r = 0; r < 4; r++) {
        float pw = hl[r][0] * wo0 + hl[r][1] * wo1;
        pw += __shfl_xor_sync(0xffffffffu, pw, 16);
        pw += __shfl_xor_sync(0xffffffffu, pw, 8);
        pw += __shfl_xor_sync(0xffffffffu, pw, 4);
        pw += __shfl_xor_sync(0xffffffffu, pw, 2);
        pw += __shfl_xor_sync(0xffffffffu, pw, 1);
        if (lane == 0) out[row0 + r] = sigp(pw + bo);
    }
}

extern "C" void kernel_launch(void* const* d_in, const int* in_sizes, int n_in,
                              void* d_out, int out_size) {
    const float* x1   = (const float*)d_in[0];
    const float* x2   = (const float*)d_in[1];
    const float* x3   = (const float*)d_in[2];
    const float* Wih3 = (const float*)d_in[3];
    const float* Whh3 = (const float*)d_in[4];
    const float* bih3 = (const float*)d_in[5];
    const float* bhh3 = (const float*)d_in[6];
    const float* Wih2 = (const float*)d_in[7];
    const float* Whh2 = (const float*)d_in[8];
    const float* bih2 = (const float*)d_in[9];
    const float* bhh2 = (const float*)d_in[10];
    const float* Wih1 = (const float*)d_in[11];
    const float* Whh1 = (const float*)d_in[12];
    const float* bih1 = (const float*)d_in[13];
    const float* bhh1 = (const float*)d_in[14];
    const float* Wout = (const float*)d_in[15];
    const float* bOut = (const float*)d_in[16];

    cudaFuncSetAttribute(mclstm_kernel, cudaFuncAttributeMaxDynamicSharedMemorySize, SMEM_BYTES);

    mclstm_kernel<<<NCTA, NTHR, SMEM_BYTES>>>(
        x1, x2, x3,
        Wih3, Whh3, bih3, bhh3,
        Wih2, Whh2, bih2, bhh2,
        Wih1, Whh1, bih1, bhh1,
        Wout, bOut, (float*)d_out);
}